// round 15
// baseline (speedup 1.0000x reference)
#include <cuda_runtime.h>
#include <cuda_fp16.h>
#include <mma.h>
#include <cstdint>

using namespace nvcuda;

#define N_ROWS 8192
#define DIM    512
#define KSEL   31    // k+1 entries kept per row
#define CAP    192   // max candidates per row before full-exact fallback

// Scratch (static device arrays; no allocs allowed).
__device__ float   g_emb[N_ROWS * DIM];          // exact fp32 normalized emb
__device__ __half  g_a0 [N_ROWS * DIM];          // fp16 rounding of emb
__device__ __half  g_s16[(size_t)N_ROWS * N_ROWS]; // fast sims, fp16 (128MB)
__device__ int     g_ccnt[N_ROWS];
__device__ int     g_cand[N_ROWS * CAP];
__device__ int     g_kidx[N_ROWS * KSEL];
__device__ float   g_kval[N_ROWS * KSEL];
__device__ int     g_ambig[N_ROWS];
__device__ int     g_list [N_ROWS];
__device__ int     g_cnt;

// ---------------------------------------------------------------------------
// Kernel 1: emb = normalize( relu(f*W1)*W2 ).  Bit-matches reference (vec2
// leaf + warp shfl_down tree + warp0 tree). Emits fp16 rounding too.
// ---------------------------------------------------------------------------
__global__ __launch_bounds__(256) void embed_kernel(
    const float* __restrict__ f,
    const float* __restrict__ w1,
    const float* __restrict__ w2)
{
    const int row  = blockIdx.x;
    const int t    = threadIdx.x;
    const int lane = t & 31;
    const int warp = t >> 5;

    if (row == 0 && t == 0) g_cnt = 0;

    const float2 v = reinterpret_cast<const float2*>(f + (size_t)row * DIM)[t];
    const float2 a = reinterpret_cast<const float2*>(w1)[t];
    const float2 b = reinterpret_cast<const float2*>(w2)[t];

    float h0 = __fmul_rn(fmaxf(__fmul_rn(v.x, a.x), 0.0f), b.x);
    float h1 = __fmul_rn(fmaxf(__fmul_rn(v.y, a.y), 0.0f), b.y);

    float acc = __fadd_rn(__fmul_rn(h0, h0), __fmul_rn(h1, h1));

    #pragma unroll
    for (int off = 16; off > 0; off >>= 1)
        acc = __fadd_rn(acc, __shfl_down_sync(0xFFFFFFFFu, acc, off));

    __shared__ float s_w[8];
    __shared__ float s_nrm;
    if (lane == 0) s_w[warp] = acc;
    __syncthreads();

    if (warp == 0) {
        float x = (lane < 8) ? s_w[lane] : 0.0f;
        #pragma unroll
        for (int off = 16; off > 0; off >>= 1)
            x = __fadd_rn(x, __shfl_down_sync(0xFFFFFFFFu, x, off));
        if (lane == 0)
            s_nrm = fmaxf(__fsqrt_rn(x), 1e-12f);
    }
    __syncthreads();

    const float nrm = s_nrm;
    float ox = __fdiv_rn(h0, nrm);
    float oy = __fdiv_rn(h1, nrm);
    reinterpret_cast<float2*>(g_emb + (size_t)row * DIM)[t] =
        make_float2(ox, oy);

    __half2 p0;
    p0.x = __float2half_rn(ox);
    p0.y = __float2half_rn(oy);
    reinterpret_cast<__half2*>(g_a0 + (size_t)row * DIM)[t] = p0;
}

// ---------------------------------------------------------------------------
// Kernel 2: FAST S0 = A0 * A0^T via wmma fp16 (single pass), sims stored as
// fp16 into g_s16. 128x128 CTA tile, 8 warps (2x4), warp tile 64x32,
// k-chunks of 32, 3-stage cp.async pipeline. Triangle grid; mirror store
// via per-warp smem transpose.
// ---------------------------------------------------------------------------
#define NB     (N_ROWS / 128)
#define NTRI   (NB * (NB + 1) / 2)
#define LDT    40                      // smem pitch in halfs (80B rows)
#define KCHK   32
#define NSTAGE (DIM / KCHK)            // 16
#define TILE_H (128 * LDT)             // halfs per tile buffer
#define DYN_B  (2 * 3 * TILE_H * 2)    // 61440 bytes
#define FRAGP  20                      // epilogue staging pitch (floats)

__device__ __forceinline__ void cp16(uint32_t sdst, const void* gsrc) {
    asm volatile("cp.async.ca.shared.global [%0], [%1], 16;" :: "r"(sdst), "l"(gsrc));
}

__global__ __launch_bounds__(256, 1) void gemm_fast()
{
    extern __shared__ __align__(128) char dyn[];
    __half* const sA = reinterpret_cast<__half*>(dyn);              // 3 bufs
    __half* const sB = reinterpret_cast<__half*>(dyn) + 3 * TILE_H; // 3 bufs
    const uint32_t sA_u = (uint32_t)__cvta_generic_to_shared(sA);
    const uint32_t sB_u = (uint32_t)__cvta_generic_to_shared(sB);

    const int t5 = blockIdx.x;
    int by = (int)((2.0 * NB + 1.0 - sqrt((2.0 * NB + 1.0) * (2.0 * NB + 1.0)
                                          - 8.0 * (double)t5)) * 0.5);
    while (by > 0      && (by * NB - (by * (by - 1)) / 2) > t5) by--;
    while (by < NB - 1 && ((by + 1) * NB - ((by + 1) * by) / 2) <= t5) by++;
    const int bx = by + (t5 - (by * NB - (by * (by - 1)) / 2));

    const int rowBase = by * 128;
    const int colBase = bx * 128;

    const int tid   = threadIdx.x;
    const int wid   = tid >> 5;
    const int lane  = tid & 31;
    const int warpM = wid & 1;
    const int warpN = wid >> 1;

    wmma::fragment<wmma::accumulator, 16, 16, 16, float> c[4][2];
    #pragma unroll
    for (int i = 0; i < 4; i++)
        #pragma unroll
        for (int j = 0; j < 2; j++)
            wmma::fill_fragment(c[i][j], 0.0f);

    auto fill = [&](int buf, int s) {
        const int kc = s * KCHK;
        #pragma unroll
        for (int l = 0; l < 4; l++) {
            const int idx  = tid + l * 256;
            const int tile = idx >> 9;
            const int rem  = idx & 511;
            const int r    = rem >> 2;
            const int cc   = rem & 3;
            const int gb   = tile ? colBase : rowBase;
            const uint32_t base = tile ? sB_u : sA_u;
            cp16(base + (uint32_t)(buf * TILE_H * 2 + r * (LDT * 2) + cc * 16),
                 g_a0 + (size_t)(gb + r) * DIM + kc + cc * 8);
        }
        asm volatile("cp.async.commit_group;");
    };

    fill(0, 0);
    fill(1, 1);

    for (int s = 0; s < NSTAGE; s++) {
        if (s + 1 < NSTAGE) asm volatile("cp.async.wait_group 1;");
        else                asm volatile("cp.async.wait_group 0;");
        __syncthreads();
        if (s + 2 < NSTAGE) fill((s + 2) % 3, s + 2);

        const int b = s % 3;
        #pragma unroll
        for (int ks = 0; ks < 2; ks++) {
            wmma::fragment<wmma::matrix_a, 16, 16, 16, __half,
                           wmma::row_major> af[4];
            wmma::fragment<wmma::matrix_b, 16, 16, 16, __half,
                           wmma::col_major> bf[2];
            #pragma unroll
            for (int i = 0; i < 4; i++)
                wmma::load_matrix_sync(af[i],
                    sA + b * TILE_H + (warpM * 64 + i * 16) * LDT + ks * 16, LDT);
            #pragma unroll
            for (int j = 0; j < 2; j++)
                wmma::load_matrix_sync(bf[j],
                    sB + b * TILE_H + (warpN * 32 + j * 16) * LDT + ks * 16, LDT);
            #pragma unroll
            for (int i = 0; i < 4; i++)
                #pragma unroll
                for (int j = 0; j < 2; j++)
                    wmma::mma_sync(c[i][j], af[i], bf[j], c[i][j]);
        }
    }

    // Epilogue: per-warp smem staging -> fp16 stores (+ mirrored transpose).
    __syncthreads();   // pipeline buffers dead; reuse dyn as staging
    float* fw = reinterpret_cast<float*>(dyn) + wid * (16 * FRAGP);

    #pragma unroll
    for (int i = 0; i < 4; i++)
        #pragma unroll
        for (int j = 0; j < 2; j++) {
            wmma::store_matrix_sync(fw, c[i][j], FRAGP, wmma::mem_row_major);
            __syncwarp();
            const int r0 = rowBase + warpM * 64 + i * 16;
            const int c0 = colBase + warpN * 32 + j * 16;

            {
                const int rr = lane >> 1;
                const int cb = (lane & 1) * 8;
                __half2 h[4];
                #pragma unroll
                for (int q = 0; q < 4; q++)
                    h[q] = __floats2half2_rn(fw[rr * FRAGP + cb + 2 * q],
                                             fw[rr * FRAGP + cb + 2 * q + 1]);
                *reinterpret_cast<uint4*>(
                    &g_s16[(size_t)(r0 + rr) * N_ROWS + c0 + cb]) =
                    *reinterpret_cast<uint4*>(h);
            }
            if (bx != by) {
                const int cc = lane >> 1;
                const int rb = (lane & 1) * 8;
                __half2 h[4];
                #pragma unroll
                for (int q = 0; q < 4; q++)
                    h[q] = __floats2half2_rn(fw[(rb + 2 * q) * FRAGP + cc],
                                             fw[(rb + 2 * q + 1) * FRAGP + cc]);
                *reinterpret_cast<uint4*>(
                    &g_s16[(size_t)(c0 + cc) * N_ROWS + r0 + rb]) =
                    *reinterpret_cast<uint4*>(h);
            }
            __syncwarp();
        }
}

// ---------------------------------------------------------------------------
__device__ __forceinline__ unsigned f2key(float v) {
    unsigned u = __float_as_uint(v);
    return (u & 0x80000000u) ? ~u : (u | 0x80000000u);
}
__device__ __forceinline__ float key2f(unsigned k) {
    unsigned u = (k & 0x80000000u) ? (k & 0x7FFFFFFFu) : ~k;
    return __uint_as_float(u);
}

// ---------------------------------------------------------------------------
// Kernel 3: per-row radix select (2 passes, 16-bit keys) on fp16 fast sims
// -> fast s31; collect { j : s_j >= s31 - margin }.
// ---------------------------------------------------------------------------
__global__ __launch_bounds__(256) void topk_cand()
{
    __shared__ unsigned short keys[N_ROWS];
    __shared__ unsigned hist[256];
    __shared__ unsigned s_prefix;
    __shared__ int      s_rem;
    __shared__ int      s_cnt;

    const int row = blockIdx.x;
    const int tid = threadIdx.x;
    const __half* __restrict__ rowp = g_s16 + (size_t)row * N_ROWS;

    for (int i = tid; i < N_ROWS / 8; i += 256) {
        uint4 v = reinterpret_cast<const uint4*>(rowp)[i];
        *reinterpret_cast<uint4*>(&keys[i * 8]) = v;   // raw half bits
    }
    if (tid == 0) s_cnt = 0;
    __syncthreads();

    unsigned prefix = 0;
    int remaining = KSEL;

    #pragma unroll
    for (int shift = 8; shift >= 0; shift -= 8) {
        hist[tid] = 0;
        __syncthreads();
        const unsigned himask = (shift == 8) ? 0u : 0xFF00u;
        for (int i = tid; i < N_ROWS; i += 256) {
            const unsigned k = keys[i];
            if ((k & himask) == prefix)
                atomicAdd(&hist[(k >> shift) & 255u], 1u);
        }
        __syncthreads();
        if (tid == 0) {
            int cum = 0, b = 255;
            for (; b >= 0; b--) {
                cum += (int)hist[b];
                if (cum >= remaining) break;
            }
            if (b < 0) b = 0;
            s_prefix = prefix | ((unsigned)b << shift);
            s_rem    = remaining - (cum - (int)hist[b]);
        }
        __syncthreads();
        prefix    = s_prefix;
        remaining = s_rem;
        __syncthreads();
    }

    const float thr  = __half2float(__ushort_as_half((unsigned short)prefix));
    const float cthr = fmaxf(__fsub_rn(thr, __fmaf_rn(4.0e-3f, thr, 3.0e-4f)), 0.0f);
    const unsigned short ckey = __half_as_ushort(__float2half_rd(cthr));

    for (int i = tid; i < N_ROWS; i += 256) {
        if (keys[i] >= ckey) {
            int p = atomicAdd(&s_cnt, 1);
            if (p < CAP) g_cand[row * CAP + p] = i;
        }
    }
    __syncthreads();

    if (tid == 0) {
        if (s_cnt > CAP) {
            g_ambig[row] = 1;
            g_ccnt[row]  = 0;
            int p = atomicAdd(&g_cnt, 1);
            g_list[p] = row;
        } else {
            g_ambig[row] = 0;
            g_ccnt[row]  = s_cnt;
        }
    }
}

// ---------------------------------------------------------------------------
// Kernel 4: exact rescoring of candidates, smem-staged (kills the L1tex
// wavefront scatter). Batches of 48 candidate columns staged coalesced into
// sCol[k][49] (conflict-free chain reads); each candidate's sim is the
// bit-identical ascending-k fp32 FMA chain. Rank (value desc, index asc).
// ---------------------------------------------------------------------------
#define BATCH 48
#define CPITCH (BATCH + 1)   // 49: (49 mod 32 = 17) -> conflict-free lanes
#define CE_DYN ((DIM + DIM * CPITCH + CAP) * 4 + CAP * 4)  // 103936 B

__global__ __launch_bounds__(128) void cand_exact()
{
    const int row = blockIdx.x;
    if (g_ambig[row]) return;

    extern __shared__ float sm[];
    float* const sRow = sm;                      // [512]
    float* const sCol = sm + DIM;                // [512][49]
    float* const sval = sCol + DIM * CPITCH;     // [CAP]
    int*   const sidx = reinterpret_cast<int*>(sval + CAP);

    const int tid = threadIdx.x;
    const int cnt = g_ccnt[row];

    for (int i = tid; i < DIM / 4; i += 128)
        reinterpret_cast<float4*>(sRow)[i] =
            reinterpret_cast<const float4*>(g_emb + (size_t)row * DIM)[i];
    __syncthreads();

    for (int b0 = 0; b0 < cnt; b0 += BATCH) {
        const int bc = min(BATCH, cnt - b0);

        // Stage bc candidate columns, coalesced: iteration l loads candidate
        // l's 2KB with 128 float4 lanes.
        for (int l = 0; l < bc; l++) {
            const int j = g_cand[row * CAP + b0 + l];
            float4 v = reinterpret_cast<const float4*>(
                g_emb + (size_t)j * DIM)[tid];
            sCol[(tid * 4 + 0) * CPITCH + l] = v.x;
            sCol[(tid * 4 + 1) * CPITCH + l] = v.y;
            sCol[(tid * 4 + 2) * CPITCH + l] = v.z;
            sCol[(tid * 4 + 3) * CPITCH + l] = v.w;
        }
        __syncthreads();

        if (tid < bc) {
            float acc = 0.0f;
            #pragma unroll 16
            for (int k = 0; k < DIM; k++)
                acc = __fmaf_rn(sRow[k], sCol[k * CPITCH + tid], acc);
            sval[b0 + tid] = acc;
            sidx[b0 + tid] = g_cand[row * CAP + b0 + tid];
        }
        __syncthreads();
    }

    for (int t = tid; t < cnt; t += 128) {
        const float v   = sval[t];
        const int   idx = sidx[t];
        int rank = 0;
        for (int m = 0; m < cnt; m++) {
            const float vm = sval[m];
            rank += (vm > v) || (vm == v && sidx[m] < idx);
        }
        if (rank < KSEL) {
            g_kidx[row * KSEL + rank] = idx;
            g_kval[row * KSEL + rank] = v;
        }
    }
}

// ---------------------------------------------------------------------------
// Kernel 5: finalize — zero the row, scatter the 31 exact relu'd values.
// ---------------------------------------------------------------------------
__global__ __launch_bounds__(256) void finalize(float* __restrict__ C)
{
    const int row = blockIdx.x;
    const int tid = threadIdx.x;
    float* __restrict__ rowp = C + (size_t)row * N_ROWS;

    const float4 z = make_float4(0.f, 0.f, 0.f, 0.f);
    #pragma unroll
    for (int l = 0; l < 8; l++)
        reinterpret_cast<float4*>(rowp)[tid + l * 256] = z;
    __syncthreads();

    if (!g_ambig[row] && tid < KSEL) {
        const int   idx = g_kidx[row * KSEL + tid];
        const float val = g_kval[row * KSEL + tid];
        rowp[idx] = fmaxf(val, 0.0f);
    }
}

// ---------------------------------------------------------------------------
// Kernel 6 (fallback, expected empty): exact full-row sims for overflow rows.
// ---------------------------------------------------------------------------
__global__ __launch_bounds__(256) void gemm_exact(float* __restrict__ C)
{
    const int cnt = g_cnt;
    const int colBase = blockIdx.x * 128;

    for (int rt = blockIdx.y; rt * 32 < cnt; rt += 8) {
        __shared__ int   ids[32];
        __shared__ float Af[32][68];
        __shared__ float Bf[64][132];

        const int tid = threadIdx.x;
        __syncthreads();
        if (tid < 32) {
            int idx = rt * 32 + tid;
            ids[tid] = (idx < cnt) ? g_list[idx] : -1;
        }
        __syncthreads();

        const int rg = tid >> 5;
        const int cg = tid & 31;

        float acc[4][4];
        #pragma unroll
        for (int i = 0; i < 4; i++)
            #pragma unroll
            for (int j = 0; j < 4; j++)
                acc[i][j] = 0.0f;

        for (int kc = 0; kc < DIM; kc += 64) {
            #pragma unroll
            for (int l = 0; l < 2; l++) {
                const int idx = tid + l * 256;
                const int r   = idx >> 4;
                const int c4  = idx & 15;
                const int gid = ids[r];
                float4 v = make_float4(0.f, 0.f, 0.f, 0.f);
                if (gid >= 0)
                    v = *reinterpret_cast<const float4*>(
                            &g_emb[(size_t)gid * DIM + kc + c4 * 4]);
                *reinterpret_cast<float4*>(&Af[r][c4 * 4]) = v;
            }
            #pragma unroll
            for (int l = 0; l < 8; l++) {
                const int idx = tid + l * 256;
                const int col = idx >> 4;
                const int c4  = idx & 15;
                float4 v = *reinterpret_cast<const float4*>(
                    &g_emb[(size_t)(colBase + col) * DIM + kc + c4 * 4]);
                Bf[c4 * 4 + 0][col] = v.x;
                Bf[c4 * 4 + 1][col] = v.y;
                Bf[c4 * 4 + 2][col] = v.z;
                Bf[c4 * 4 + 3][col] = v.w;
            }
            __syncthreads();

            for (int k = 0; k < 64; k++) {
                float ar[4];
                #pragma unroll
                for (int i = 0; i < 4; i++) ar[i] = Af[rg * 4 + i][k];
                float4 br = *reinterpret_cast<const float4*>(&Bf[k][cg * 4]);
                #pragma unroll
                for (int i = 0; i < 4; i++) {
                    acc[i][0] = __fmaf_rn(ar[i], br.x, acc[i][0]);
                    acc[i][1] = __fmaf_rn(ar[i], br.y, acc[i][1]);
                    acc[i][2] = __fmaf_rn(ar[i], br.z, acc[i][2]);
                    acc[i][3] = __fmaf_rn(ar[i], br.w, acc[i][3]);
                }
            }
            __syncthreads();
        }

        #pragma unroll
        for (int i = 0; i < 4; i++) {
            const int gid = ids[rg * 4 + i];
            if (gid >= 0)
                *reinterpret_cast<float4*>(
                    &C[(size_t)gid * N_ROWS + colBase + cg * 4]) =
                    make_float4(acc[i][0], acc[i][1], acc[i][2], acc[i][3]);
        }
    }
}

// ---------------------------------------------------------------------------
// Kernel 7 (fallback): exact top-k (jax tie-break) on overflow rows only.
// ---------------------------------------------------------------------------
#define MAX_TIES 64

__global__ __launch_bounds__(256) void topk_final(float* __restrict__ C)
{
    const int row = blockIdx.x;
    if (!g_ambig[row]) return;

    __shared__ unsigned keys[N_ROWS];
    __shared__ unsigned hist[256];
    __shared__ unsigned s_prefix;
    __shared__ int      s_rem;
    __shared__ int      eq_idx[MAX_TIES];
    __shared__ int      eq_n;

    const int tid = threadIdx.x;
    float* __restrict__ rowp = C + (size_t)row * N_ROWS;

    for (int i = tid; i < N_ROWS; i += 256)
        keys[i] = f2key(rowp[i]);
    if (tid == 0) eq_n = 0;
    __syncthreads();

    unsigned prefix = 0;
    int remaining = KSEL;

    #pragma unroll
    for (int shift = 24; shift >= 0; shift -= 8) {
        hist[tid] = 0;
        __syncthreads();
        const unsigned himask = (shift == 24) ? 0u : (0xFFFFFFFFu << (shift + 8));
        for (int i = tid; i < N_ROWS; i += 256) {
            const unsigned k = keys[i];
            if ((k & himask) == prefix)
                atomicAdd(&hist[(k >> shift) & 255u], 1u);
        }
        __syncthreads();
        if (tid == 0) {
            int cum = 0, b = 255;
            for (; b >= 0; b--) {
                cum += (int)hist[b];
                if (cum >= remaining) break;
            }
            if (b < 0) b = 0;
            s_prefix = prefix | ((unsigned)b << shift);
            s_rem    = remaining - (cum - (int)hist[b]);
        }
        __syncthreads();
        prefix    = s_prefix;
        remaining = s_rem;
        __syncthreads();
    }

    for (int i = tid; i < N_ROWS; i += 256) {
        if (keys[i] == prefix) {
            int p = atomicAdd(&eq_n, 1);
            if (p < MAX_TIES) eq_idx[p] = i;
        }
    }
    __syncthreads();
    const int m = eq_n;

    for (int i = tid; i < N_ROWS; i += 256) {
        const unsigned k = keys[i];
        float out = 0.0f;
        if (k > prefix) {
            out = fmaxf(key2f(k), 0.0f);
        } else if (k == prefix) {
            bool keep;
            if (m <= remaining || m > MAX_TIES) {
                keep = true;
            } else {
                int r = 0;
                for (int j = 0; j < m; j++) r += (eq_idx[j] < i);
                keep = (r < remaining);
            }
            if (keep) out = fmaxf(key2f(k), 0.0f);
        }
        rowp[i] = out;
    }
}

// ---------------------------------------------------------------------------
extern "C" void kernel_launch(void* const* d_in, const int* in_sizes, int n_in,
                              void* d_out, int out_size)
{
    const float* features = (const float*)d_in[0];  // [8192, 512]
    const float* W1       = (const float*)d_in[1];  // [512]
    const float* W2       = (const float*)d_in[2];  // [512]
    float* out            = (float*)d_out;          // [8192, 8192]

    cudaFuncSetAttribute(gemm_fast,
                         cudaFuncAttributeMaxDynamicSharedMemorySize, DYN_B);
    cudaFuncSetAttribute(cand_exact,
                         cudaFuncAttributeMaxDynamicSharedMemorySize, CE_DYN);

    embed_kernel<<<N_ROWS, 256>>>(features, W1, W2);
    gemm_fast<<<NTRI, 256, DYN_B>>>();
    topk_cand<<<N_ROWS, 256>>>();
    cand_exact<<<N_ROWS, 128, CE_DYN>>>();
    finalize<<<N_ROWS, 256>>>(out);
    gemm_exact<<<dim3(64, 8), 256>>>(out);   // fallback (expected empty)
    topk_final<<<N_ROWS, 256>>>(out);        // fallback (expected empty)
}

// round 16
// speedup vs baseline: 1.2516x; 1.2516x over previous
#include <cuda_runtime.h>
#include <cuda_fp16.h>
#include <mma.h>
#include <cstdint>

using namespace nvcuda;

#define N_ROWS 8192
#define DIM    512
#define KSEL   31    // k+1 entries kept per row
#define CAP    192   // max candidates per row before full-exact fallback

// Scratch (static device arrays; no allocs allowed).
__device__ float   g_emb[N_ROWS * DIM];          // exact fp32 normalized emb
__device__ __half  g_a0 [N_ROWS * DIM];          // fp16 rounding of emb
__device__ __half  g_s16[(size_t)N_ROWS * N_ROWS]; // fast sims, fp16 (128MB)
__device__ int     g_ccnt[N_ROWS];
__device__ int     g_cand[N_ROWS * CAP];
__device__ int     g_kidx[N_ROWS * KSEL];
__device__ float   g_kval[N_ROWS * KSEL];
__device__ int     g_ambig[N_ROWS];
__device__ int     g_list [N_ROWS];
__device__ int     g_cnt;

// ---------------------------------------------------------------------------
// Kernel 1: emb = normalize( relu(f*W1)*W2 ).  Bit-matches reference (vec2
// leaf + warp shfl_down tree + warp0 tree). Emits fp16 rounding too.
// ---------------------------------------------------------------------------
__global__ __launch_bounds__(256) void embed_kernel(
    const float* __restrict__ f,
    const float* __restrict__ w1,
    const float* __restrict__ w2)
{
    const int row  = blockIdx.x;
    const int t    = threadIdx.x;
    const int lane = t & 31;
    const int warp = t >> 5;

    if (row == 0 && t == 0) g_cnt = 0;

    const float2 v = reinterpret_cast<const float2*>(f + (size_t)row * DIM)[t];
    const float2 a = reinterpret_cast<const float2*>(w1)[t];
    const float2 b = reinterpret_cast<const float2*>(w2)[t];

    float h0 = __fmul_rn(fmaxf(__fmul_rn(v.x, a.x), 0.0f), b.x);
    float h1 = __fmul_rn(fmaxf(__fmul_rn(v.y, a.y), 0.0f), b.y);

    float acc = __fadd_rn(__fmul_rn(h0, h0), __fmul_rn(h1, h1));

    #pragma unroll
    for (int off = 16; off > 0; off >>= 1)
        acc = __fadd_rn(acc, __shfl_down_sync(0xFFFFFFFFu, acc, off));

    __shared__ float s_w[8];
    __shared__ float s_nrm;
    if (lane == 0) s_w[warp] = acc;
    __syncthreads();

    if (warp == 0) {
        float x = (lane < 8) ? s_w[lane] : 0.0f;
        #pragma unroll
        for (int off = 16; off > 0; off >>= 1)
            x = __fadd_rn(x, __shfl_down_sync(0xFFFFFFFFu, x, off));
        if (lane == 0)
            s_nrm = fmaxf(__fsqrt_rn(x), 1e-12f);
    }
    __syncthreads();

    const float nrm = s_nrm;
    float ox = __fdiv_rn(h0, nrm);
    float oy = __fdiv_rn(h1, nrm);
    reinterpret_cast<float2*>(g_emb + (size_t)row * DIM)[t] =
        make_float2(ox, oy);

    __half2 p0;
    p0.x = __float2half_rn(ox);
    p0.y = __float2half_rn(oy);
    reinterpret_cast<__half2*>(g_a0 + (size_t)row * DIM)[t] = p0;
}

// ---------------------------------------------------------------------------
// Kernel 2: FAST S0 = A0 * A0^T via wmma fp16 (single pass), sims stored as
// fp16 into g_s16. 128x128 CTA tile, 8 warps (2x4), warp tile 64x32,
// k-chunks of 32, 3-stage cp.async pipeline. Triangle grid; mirror store
// via per-warp smem transpose.
// ---------------------------------------------------------------------------
#define NB     (N_ROWS / 128)
#define NTRI   (NB * (NB + 1) / 2)
#define LDT    40                      // smem pitch in halfs (80B rows)
#define KCHK   32
#define NSTAGE (DIM / KCHK)            // 16
#define TILE_H (128 * LDT)             // halfs per tile buffer
#define DYN_B  (2 * 3 * TILE_H * 2)    // 61440 bytes
#define FRAGP  20                      // epilogue staging pitch (floats)

__device__ __forceinline__ void cp16(uint32_t sdst, const void* gsrc) {
    asm volatile("cp.async.ca.shared.global [%0], [%1], 16;" :: "r"(sdst), "l"(gsrc));
}

__global__ __launch_bounds__(256, 1) void gemm_fast()
{
    extern __shared__ __align__(128) char dyn[];
    __half* const sA = reinterpret_cast<__half*>(dyn);              // 3 bufs
    __half* const sB = reinterpret_cast<__half*>(dyn) + 3 * TILE_H; // 3 bufs
    const uint32_t sA_u = (uint32_t)__cvta_generic_to_shared(sA);
    const uint32_t sB_u = (uint32_t)__cvta_generic_to_shared(sB);

    const int t5 = blockIdx.x;
    int by = (int)((2.0 * NB + 1.0 - sqrt((2.0 * NB + 1.0) * (2.0 * NB + 1.0)
                                          - 8.0 * (double)t5)) * 0.5);
    while (by > 0      && (by * NB - (by * (by - 1)) / 2) > t5) by--;
    while (by < NB - 1 && ((by + 1) * NB - ((by + 1) * by) / 2) <= t5) by++;
    const int bx = by + (t5 - (by * NB - (by * (by - 1)) / 2));

    const int rowBase = by * 128;
    const int colBase = bx * 128;

    const int tid   = threadIdx.x;
    const int wid   = tid >> 5;
    const int lane  = tid & 31;
    const int warpM = wid & 1;
    const int warpN = wid >> 1;

    wmma::fragment<wmma::accumulator, 16, 16, 16, float> c[4][2];
    #pragma unroll
    for (int i = 0; i < 4; i++)
        #pragma unroll
        for (int j = 0; j < 2; j++)
            wmma::fill_fragment(c[i][j], 0.0f);

    auto fill = [&](int buf, int s) {
        const int kc = s * KCHK;
        #pragma unroll
        for (int l = 0; l < 4; l++) {
            const int idx  = tid + l * 256;
            const int tile = idx >> 9;
            const int rem  = idx & 511;
            const int r    = rem >> 2;
            const int cc   = rem & 3;
            const int gb   = tile ? colBase : rowBase;
            const uint32_t base = tile ? sB_u : sA_u;
            cp16(base + (uint32_t)(buf * TILE_H * 2 + r * (LDT * 2) + cc * 16),
                 g_a0 + (size_t)(gb + r) * DIM + kc + cc * 8);
        }
        asm volatile("cp.async.commit_group;");
    };

    fill(0, 0);
    fill(1, 1);

    for (int s = 0; s < NSTAGE; s++) {
        if (s + 1 < NSTAGE) asm volatile("cp.async.wait_group 1;");
        else                asm volatile("cp.async.wait_group 0;");
        __syncthreads();
        if (s + 2 < NSTAGE) fill((s + 2) % 3, s + 2);

        const int b = s % 3;
        #pragma unroll
        for (int ks = 0; ks < 2; ks++) {
            wmma::fragment<wmma::matrix_a, 16, 16, 16, __half,
                           wmma::row_major> af[4];
            wmma::fragment<wmma::matrix_b, 16, 16, 16, __half,
                           wmma::col_major> bf[2];
            #pragma unroll
            for (int i = 0; i < 4; i++)
                wmma::load_matrix_sync(af[i],
                    sA + b * TILE_H + (warpM * 64 + i * 16) * LDT + ks * 16, LDT);
            #pragma unroll
            for (int j = 0; j < 2; j++)
                wmma::load_matrix_sync(bf[j],
                    sB + b * TILE_H + (warpN * 32 + j * 16) * LDT + ks * 16, LDT);
            #pragma unroll
            for (int i = 0; i < 4; i++)
                #pragma unroll
                for (int j = 0; j < 2; j++)
                    wmma::mma_sync(c[i][j], af[i], bf[j], c[i][j]);
        }
    }

    // Epilogue: per-warp smem staging -> fp16 stores (+ mirrored transpose).
    __syncthreads();   // pipeline buffers dead; reuse dyn as staging
    float* fw = reinterpret_cast<float*>(dyn) + wid * (16 * FRAGP);

    #pragma unroll
    for (int i = 0; i < 4; i++)
        #pragma unroll
        for (int j = 0; j < 2; j++) {
            wmma::store_matrix_sync(fw, c[i][j], FRAGP, wmma::mem_row_major);
            __syncwarp();
            const int r0 = rowBase + warpM * 64 + i * 16;
            const int c0 = colBase + warpN * 32 + j * 16;

            {
                const int rr = lane >> 1;
                const int cb = (lane & 1) * 8;
                __half2 h[4];
                #pragma unroll
                for (int q = 0; q < 4; q++)
                    h[q] = __floats2half2_rn(fw[rr * FRAGP + cb + 2 * q],
                                             fw[rr * FRAGP + cb + 2 * q + 1]);
                *reinterpret_cast<uint4*>(
                    &g_s16[(size_t)(r0 + rr) * N_ROWS + c0 + cb]) =
                    *reinterpret_cast<uint4*>(h);
            }
            if (bx != by) {
                const int cc = lane >> 1;
                const int rb = (lane & 1) * 8;
                __half2 h[4];
                #pragma unroll
                for (int q = 0; q < 4; q++)
                    h[q] = __floats2half2_rn(fw[(rb + 2 * q) * FRAGP + cc],
                                             fw[(rb + 2 * q + 1) * FRAGP + cc]);
                *reinterpret_cast<uint4*>(
                    &g_s16[(size_t)(c0 + cc) * N_ROWS + r0 + rb]) =
                    *reinterpret_cast<uint4*>(h);
            }
            __syncwarp();
        }
}

// ---------------------------------------------------------------------------
__device__ __forceinline__ unsigned f2key(float v) {
    unsigned u = __float_as_uint(v);
    return (u & 0x80000000u) ? ~u : (u | 0x80000000u);
}
__device__ __forceinline__ float key2f(unsigned k) {
    unsigned u = (k & 0x80000000u) ? (k & 0x7FFFFFFFu) : ~k;
    return __uint_as_float(u);
}

// ---------------------------------------------------------------------------
// Kernel 3: per-row radix select (2 passes, 16-bit keys) on fp16 fast sims
// -> fast s31; collect { j : s_j >= s31 - margin }. ALSO zeroes the output
// row of C (DRAM writes overlap the radix compute; finalize only scatters).
// ---------------------------------------------------------------------------
__global__ __launch_bounds__(256) void topk_cand(float* __restrict__ C)
{
    __shared__ unsigned short keys[N_ROWS];
    __shared__ unsigned hist[256];
    __shared__ unsigned s_prefix;
    __shared__ int      s_rem;
    __shared__ int      s_cnt;

    const int row = blockIdx.x;
    const int tid = threadIdx.x;
    const __half* __restrict__ rowp = g_s16 + (size_t)row * N_ROWS;
    float* __restrict__ outp = C + (size_t)row * N_ROWS;

    for (int i = tid; i < N_ROWS / 8; i += 256) {
        uint4 v = reinterpret_cast<const uint4*>(rowp)[i];
        *reinterpret_cast<uint4*>(&keys[i * 8]) = v;   // raw half bits
    }
    if (tid == 0) s_cnt = 0;

    // Zero the output row now; the stores drain on the DRAM pipe while the
    // radix histograms below run on ALU/SMEM.
    {
        const float4 z = make_float4(0.f, 0.f, 0.f, 0.f);
        #pragma unroll
        for (int l = 0; l < 8; l++)
            reinterpret_cast<float4*>(outp)[tid + l * 256] = z;
    }
    __syncthreads();

    unsigned prefix = 0;
    int remaining = KSEL;

    #pragma unroll
    for (int shift = 8; shift >= 0; shift -= 8) {
        hist[tid] = 0;
        __syncthreads();
        const unsigned himask = (shift == 8) ? 0u : 0xFF00u;
        for (int i = tid; i < N_ROWS; i += 256) {
            const unsigned k = keys[i];
            if ((k & himask) == prefix)
                atomicAdd(&hist[(k >> shift) & 255u], 1u);
        }
        __syncthreads();
        if (tid == 0) {
            int cum = 0, b = 255;
            for (; b >= 0; b--) {
                cum += (int)hist[b];
                if (cum >= remaining) break;
            }
            if (b < 0) b = 0;
            s_prefix = prefix | ((unsigned)b << shift);
            s_rem    = remaining - (cum - (int)hist[b]);
        }
        __syncthreads();
        prefix    = s_prefix;
        remaining = s_rem;
        __syncthreads();
    }

    const float thr  = __half2float(__ushort_as_half((unsigned short)prefix));
    const float cthr = fmaxf(__fsub_rn(thr, __fmaf_rn(4.0e-3f, thr, 3.0e-4f)), 0.0f);
    const unsigned short ckey = __half_as_ushort(__float2half_rd(cthr));

    for (int i = tid; i < N_ROWS; i += 256) {
        if (keys[i] >= ckey) {
            int p = atomicAdd(&s_cnt, 1);
            if (p < CAP) g_cand[row * CAP + p] = i;
        }
    }
    __syncthreads();

    if (tid == 0) {
        if (s_cnt > CAP) {
            g_ambig[row] = 1;
            g_ccnt[row]  = 0;
            int p = atomicAdd(&g_cnt, 1);
            g_list[p] = row;
        } else {
            g_ambig[row] = 0;
            g_ccnt[row]  = s_cnt;
        }
    }
}

// ---------------------------------------------------------------------------
// Kernel 4: exact rescoring of candidates (R14 shape: 1 row / 128-thr block,
// direct global gathers — best measured variant). Bit-identical ascending-k
// fp32 FMA chain; rank (value desc, index asc).
// ---------------------------------------------------------------------------
__global__ __launch_bounds__(128) void cand_exact()
{
    const int row = blockIdx.x;
    if (g_ambig[row]) return;

    __shared__ float sRow[DIM];
    __shared__ float sval[CAP];
    __shared__ int   sidx[CAP];

    const int tid = threadIdx.x;
    const int cnt = g_ccnt[row];

    for (int i = tid; i < DIM / 4; i += 128)
        reinterpret_cast<float4*>(sRow)[i] =
            reinterpret_cast<const float4*>(g_emb + (size_t)row * DIM)[i];
    __syncthreads();

    for (int t = tid; t < cnt; t += 128) {
        const int j = g_cand[row * CAP + t];
        const float4* col = reinterpret_cast<const float4*>(g_emb + (size_t)j * DIM);
        float acc = 0.0f;
        #pragma unroll 8
        for (int k4 = 0; k4 < DIM / 4; k4++) {
            const float4 cv = col[k4];
            const float4 rv = reinterpret_cast<const float4*>(sRow)[k4];
            acc = __fmaf_rn(rv.x, cv.x, acc);
            acc = __fmaf_rn(rv.y, cv.y, acc);
            acc = __fmaf_rn(rv.z, cv.z, acc);
            acc = __fmaf_rn(rv.w, cv.w, acc);
        }
        sval[t] = acc;
        sidx[t] = j;
    }
    __syncthreads();

    for (int t = tid; t < cnt; t += 128) {
        const float v   = sval[t];
        const int   idx = sidx[t];
        int rank = 0;
        for (int m = 0; m < cnt; m++) {
            const float vm = sval[m];
            rank += (vm > v) || (vm == v && sidx[m] < idx);
        }
        if (rank < KSEL) {
            g_kidx[row * KSEL + rank] = idx;
            g_kval[row * KSEL + rank] = v;
        }
    }
}

// ---------------------------------------------------------------------------
// Kernel 5: finalize — scatter the 31 exact relu'd values (rows pre-zeroed
// in topk_cand). One warp per row, 8 rows per block.
// ---------------------------------------------------------------------------
__global__ __launch_bounds__(256) void finalize(float* __restrict__ C)
{
    const int tid  = threadIdx.x;
    const int row  = blockIdx.x * 8 + (tid >> 5);
    const int lane = tid & 31;

    if (g_ambig[row]) return;
    if (lane < KSEL) {
        const int   idx = g_kidx[row * KSEL + lane];
        const float val = g_kval[row * KSEL + lane];
        C[(size_t)row * N_ROWS + idx] = fmaxf(val, 0.0f);
    }
}

// ---------------------------------------------------------------------------
// Kernel 6 (fallback, expected empty): exact full-row sims for overflow rows.
// ---------------------------------------------------------------------------
__global__ __launch_bounds__(256) void gemm_exact(float* __restrict__ C)
{
    const int cnt = g_cnt;
    const int colBase = blockIdx.x * 128;

    for (int rt = blockIdx.y; rt * 32 < cnt; rt += 8) {
        __shared__ int   ids[32];
        __shared__ float Af[32][68];
        __shared__ float Bf[64][132];

        const int tid = threadIdx.x;
        __syncthreads();
        if (tid < 32) {
            int idx = rt * 32 + tid;
            ids[tid] = (idx < cnt) ? g_list[idx] : -1;
        }
        __syncthreads();

        const int rg = tid >> 5;
        const int cg = tid & 31;

        float acc[4][4];
        #pragma unroll
        for (int i = 0; i < 4; i++)
            #pragma unroll
            for (int j = 0; j < 4; j++)
                acc[i][j] = 0.0f;

        for (int kc = 0; kc < DIM; kc += 64) {
            #pragma unroll
            for (int l = 0; l < 2; l++) {
                const int idx = tid + l * 256;
                const int r   = idx >> 4;
                const int c4  = idx & 15;
                const int gid = ids[r];
                float4 v = make_float4(0.f, 0.f, 0.f, 0.f);
                if (gid >= 0)
                    v = *reinterpret_cast<const float4*>(
                            &g_emb[(size_t)gid * DIM + kc + c4 * 4]);
                *reinterpret_cast<float4*>(&Af[r][c4 * 4]) = v;
            }
            #pragma unroll
            for (int l = 0; l < 8; l++) {
                const int idx = tid + l * 256;
                const int col = idx >> 4;
                const int c4  = idx & 15;
                float4 v = *reinterpret_cast<const float4*>(
                    &g_emb[(size_t)(colBase + col) * DIM + kc + c4 * 4]);
                Bf[c4 * 4 + 0][col] = v.x;
                Bf[c4 * 4 + 1][col] = v.y;
                Bf[c4 * 4 + 2][col] = v.z;
                Bf[c4 * 4 + 3][col] = v.w;
            }
            __syncthreads();

            for (int k = 0; k < 64; k++) {
                float ar[4];
                #pragma unroll
                for (int i = 0; i < 4; i++) ar[i] = Af[rg * 4 + i][k];
                float4 br = *reinterpret_cast<const float4*>(&Bf[k][cg * 4]);
                #pragma unroll
                for (int i = 0; i < 4; i++) {
                    acc[i][0] = __fmaf_rn(ar[i], br.x, acc[i][0]);
                    acc[i][1] = __fmaf_rn(ar[i], br.y, acc[i][1]);
                    acc[i][2] = __fmaf_rn(ar[i], br.z, acc[i][2]);
                    acc[i][3] = __fmaf_rn(ar[i], br.w, acc[i][3]);
                }
            }
            __syncthreads();
        }

        #pragma unroll
        for (int i = 0; i < 4; i++) {
            const int gid = ids[rg * 4 + i];
            if (gid >= 0)
                *reinterpret_cast<float4*>(
                    &C[(size_t)gid * N_ROWS + colBase + cg * 4]) =
                    make_float4(acc[i][0], acc[i][1], acc[i][2], acc[i][3]);
        }
    }
}

// ---------------------------------------------------------------------------
// Kernel 7 (fallback): exact top-k (jax tie-break) on overflow rows only.
// ---------------------------------------------------------------------------
#define MAX_TIES 64

__global__ __launch_bounds__(256) void topk_final(float* __restrict__ C)
{
    const int row = blockIdx.x;
    if (!g_ambig[row]) return;

    __shared__ unsigned keys[N_ROWS];
    __shared__ unsigned hist[256];
    __shared__ unsigned s_prefix;
    __shared__ int      s_rem;
    __shared__ int      eq_idx[MAX_TIES];
    __shared__ int      eq_n;

    const int tid = threadIdx.x;
    float* __restrict__ rowp = C + (size_t)row * N_ROWS;

    for (int i = tid; i < N_ROWS; i += 256)
        keys[i] = f2key(rowp[i]);
    if (tid == 0) eq_n = 0;
    __syncthreads();

    unsigned prefix = 0;
    int remaining = KSEL;

    #pragma unroll
    for (int shift = 24; shift >= 0; shift -= 8) {
        hist[tid] = 0;
        __syncthreads();
        const unsigned himask = (shift == 24) ? 0u : (0xFFFFFFFFu << (shift + 8));
        for (int i = tid; i < N_ROWS; i += 256) {
            const unsigned k = keys[i];
            if ((k & himask) == prefix)
                atomicAdd(&hist[(k >> shift) & 255u], 1u);
        }
        __syncthreads();
        if (tid == 0) {
            int cum = 0, b = 255;
            for (; b >= 0; b--) {
                cum += (int)hist[b];
                if (cum >= remaining) break;
            }
            if (b < 0) b = 0;
            s_prefix = prefix | ((unsigned)b << shift);
            s_rem    = remaining - (cum - (int)hist[b]);
        }
        __syncthreads();
        prefix    = s_prefix;
        remaining = s_rem;
        __syncthreads();
    }

    for (int i = tid; i < N_ROWS; i += 256) {
        if (keys[i] == prefix) {
            int p = atomicAdd(&eq_n, 1);
            if (p < MAX_TIES) eq_idx[p] = i;
        }
    }
    __syncthreads();
    const int m = eq_n;

    for (int i = tid; i < N_ROWS; i += 256) {
        const unsigned k = keys[i];
        float out = 0.0f;
        if (k > prefix) {
            out = fmaxf(key2f(k), 0.0f);
        } else if (k == prefix) {
            bool keep;
            if (m <= remaining || m > MAX_TIES) {
                keep = true;
            } else {
                int r = 0;
                for (int j = 0; j < m; j++) r += (eq_idx[j] < i);
                keep = (r < remaining);
            }
            if (keep) out = fmaxf(key2f(k), 0.0f);
        }
        rowp[i] = out;
    }
}

// ---------------------------------------------------------------------------
extern "C" void kernel_launch(void* const* d_in, const int* in_sizes, int n_in,
                              void* d_out, int out_size)
{
    const float* features = (const float*)d_in[0];  // [8192, 512]
    const float* W1       = (const float*)d_in[1];  // [512]
    const float* W2       = (const float*)d_in[2];  // [512]
    float* out            = (float*)d_out;          // [8192, 8192]

    cudaFuncSetAttribute(gemm_fast,
                         cudaFuncAttributeMaxDynamicSharedMemorySize, DYN_B);

    embed_kernel<<<N_ROWS, 256>>>(features, W1, W2);
    gemm_fast<<<NTRI, 256, DYN_B>>>();
    topk_cand<<<N_ROWS, 256>>>(out);
    cand_exact<<<N_ROWS, 128>>>();
    finalize<<<N_ROWS / 8, 256>>>(out);
    gemm_exact<<<dim3(64, 8), 256>>>(out);   // fallback (expected empty)
    topk_final<<<N_ROWS, 256>>>(out);        // fallback (expected empty)
}